// round 14
// baseline (speedup 1.0000x reference)
#include <cuda_runtime.h>
#include <cuda_fp16.h>
#include <cstdint>

// ---------------- problem constants ----------------
#define B_TOT 2048
#define P_    80
#define FIN   138
#define NTILE 2560                   // 80 p x 32 b-tiles
#define NCTA  296                    // 148 SM x occ 2

// ---------------- packed fp16 weight image ----------------
// Per n row, per k32 tile: 64B = 32 fp16. layout: [p][kt][nc(2)][n(256)][64B]
__device__ __align__(1024) unsigned char g_w1pk[(size_t)10485760];   // 80*4*2*256*64
__device__ __align__(1024) unsigned char g_w2pk[(size_t)41943040];   // 80*16*2*256*64

// ---------------- smem layout (bytes) ----------------
// A rows (64): [0,1024) fp16 x512 (h1; zc overlay at +512 for layer 1) + 16 pad
#define H1STR 1040
#define SM_A    0                    // 64*1040 = 66560
#define BSTR  80                     // 64B data + 16 pad (conflict-free ldsm)
#define BBUF  20480                  // 256 rows * 80
#define SM_BS   66560                // 2*BBUF = 40960
#define SM_YS   107520
#define SM_IDX  107776
#define SM_B1   108288
#define SM_B2   110336
#define SM_W3   112384
#define SMEM_TOTAL 114432            // x2 CTAs = 223.5 KB <= 228 KB/SM

// ---------------- helpers ----------------
__device__ __forceinline__ void cp16s(uint32_t dst, const void* src) {
    asm volatile("cp.async.cg.shared.global [%0], [%1], 16;" :: "r"(dst), "l"(src));
}
__device__ __forceinline__ void cp_commit() { asm volatile("cp.async.commit_group;"); }
__device__ __forceinline__ void cp_wait0()  { asm volatile("cp.async.wait_group 0;"); }

__device__ __forceinline__ void ldsm4(uint32_t* r, uint32_t addr) {
    asm volatile("ldmatrix.sync.aligned.m8n8.x4.shared.b16 {%0,%1,%2,%3}, [%4];"
        : "=r"(r[0]), "=r"(r[1]), "=r"(r[2]), "=r"(r[3]) : "r"(addr));
}
__device__ __forceinline__ void mma_f16(float* c, const uint32_t* a, const uint32_t* b) {
    asm volatile(
        "mma.sync.aligned.m16n8k16.row.col.f32.f16.f16.f32 "
        "{%0,%1,%2,%3}, {%4,%5,%6,%7}, {%8,%9}, {%0,%1,%2,%3};"
        : "+f"(c[0]), "+f"(c[1]), "+f"(c[2]), "+f"(c[3])
        : "r"(a[0]), "r"(a[1]), "r"(a[2]), "r"(a[3]), "r"(b[0]), "r"(b[1]));
}
__device__ __forceinline__ uint32_t pkh(float x0, float x1) {
    __half2 v = __floats2half2_rn(x0, x1);
    return *reinterpret_cast<uint32_t*>(&v);
}

// issue stage-0 load of a segment into buffer 0 (one cp.async group)
__device__ __forceinline__ void preload(uint32_t bsWrite, const unsigned char* g, int tid) {
    #pragma unroll
    for (int r = 0; r < 4; r++) {
        int i = tid + r * 256;
        cp16s(bsWrite + (uint32_t)((i >> 2) * BSTR + (i & 3) * 16), g + (size_t)i * 16);
    }
    cp_commit();
}

// ---------------- core GEMM: acc(64x256) += A(fp16) x B(fp16), k32 stages ------
// Stage 0 of gsrc must already be in flight. Last stage prefetches stage 0 of
// gnext (if non-null) into buffer 0 — chains across segments AND tiles.
template<int NST>
__device__ __forceinline__ void gemm1p(
    float acc[2][8][4], uint32_t aHi,
    uint32_t bBase, uint32_t bsWrite,
    const unsigned char* __restrict__ gsrc,
    const unsigned char* __restrict__ gnext, int tid)
{
    #pragma unroll 1
    for (int s = 0; s < NST; s++) {
        cp_wait0();
        __syncthreads();
        const unsigned char* pf = (s + 1 < NST) ? gsrc + (size_t)(s + 1) * 32768 : gnext;
        if (pf) {
            uint32_t wd = bsWrite + (uint32_t)(((s + 1) & 1) * BBUF);
            #pragma unroll
            for (int r = 0; r < 4; r++) {
                int i = tid + r * 256;
                cp16s(wd + (uint32_t)((i >> 2) * BSTR + (i & 3) * 16), pf + (size_t)i * 16);
            }
        }
        cp_commit();   // exactly one group per stage (possibly empty at the very end)

        const uint32_t bb = bBase + (uint32_t)((s & 1) * BBUF);

        #pragma unroll
        for (int t = 0; t < 2; t++) {
            uint32_t ah[2][4];
            ldsm4(ah[0], aHi + (uint32_t)(s * 64 + t * 32));
            ldsm4(ah[1], aHi + (uint32_t)(16 * H1STR + s * 64 + t * 32));
            uint32_t bh[4][4];
            #pragma unroll
            for (int q = 0; q < 4; q++)
                ldsm4(bh[q], bb + (uint32_t)(q * 16 * BSTR + t * 32));
            #pragma unroll
            for (int nt = 0; nt < 8; nt++) {
                const uint32_t* bf = &bh[nt >> 1][(nt & 1) * 2];
                mma_f16(acc[0][nt], ah[0], bf);
                mma_f16(acc[1][nt], ah[1], bf);
            }
        }
    }
}

// ---------------- prep: weights -> fp16 rows; tail blocks init out=b3 ---------
extern "C" __global__ void __launch_bounds__(256)
prep_kernel(const float* __restrict__ W1, const float* __restrict__ W2,
            const float* __restrict__ b3, float* __restrict__ out)
{
    int j = blockIdx.x;
    int tid = threadIdx.x;
    if (j >= 3200) {                             // out init: 640 blocks x 256 = 163840
        int i = (j - 3200) * 256 + tid;
        out[i] = b3[i % P_];
        return;
    }
    const float* src;
    unsigned char* dst;
    if (j < 640) {                               // W1: (p, kt 0..3, nc)
        int nc = j & 1, kt = (j >> 1) & 3, p = j >> 3;
        src = W1 + ((size_t)p * FIN + 10 + kt * 32) * 512 + nc * 256;
        dst = g_w1pk + (size_t)p * 131072 + (size_t)kt * 32768 + (size_t)nc * 16384;
    } else {                                     // W2: (p, kt 0..15, nc)
        int q = j - 640;
        int nc = q & 1, kt = (q >> 1) & 15, p = q >> 5;
        src = W2 + ((size_t)p * 512 + kt * 32) * 512 + nc * 256;
        dst = g_w2pk + (size_t)p * 524288 + (size_t)kt * 32768 + (size_t)nc * 16384;
    }
    uint32_t wdat[16];
    #pragma unroll
    for (int i = 0; i < 16; i++) {
        float v0 = src[(size_t)(2 * i) * 512 + tid];
        float v1 = src[(size_t)(2 * i + 1) * 512 + tid];
        wdat[i] = pkh(v0, v1);
    }
    uint4* d = (uint4*)(dst + (size_t)tid * 64);
    #pragma unroll
    for (int r = 0; r < 4; r++)
        d[r] = make_uint4(wdat[r * 4], wdat[r * 4 + 1], wdat[r * 4 + 2], wdat[r * 4 + 3]);
}

// ---------------- main: persistent CTAs over (bt, p) tiles ----------------
extern "C" __global__ void __launch_bounds__(256, 2)
mc_main(const int* __restrict__ y, const float* __restrict__ zL, const float* __restrict__ zR,
        const int* __restrict__ idxL, const int* __restrict__ idxR,
        const float* __restrict__ W1, const float* __restrict__ b1,
        const float* __restrict__ b2, const float* __restrict__ W3,
        float* __restrict__ out)
{
    extern __shared__ char sm[];
    const uint32_t smb = (uint32_t)__cvta_generic_to_shared(sm);
    int*   ys   = (int*)(sm + SM_YS);
    int*   idxs = (int*)(sm + SM_IDX);
    float* b1s  = (float*)(sm + SM_B1);
    float* b2s  = (float*)(sm + SM_B2);
    float* w3s  = (float*)(sm + SM_W3);

    const int tid = threadIdx.x, l = tid & 31, w = tid >> 5;
    const int mbase = (w >> 2) * 32, nbase = (w & 3) * 64;
    const int lr = l >> 2;
    const uint32_t bsWrite = smb + SM_BS;
    const uint32_t aRowOff = (uint32_t)((mbase + (l & 15)) * H1STR + (l >> 4) * 16);
    const uint32_t aHi1 = smb + SM_A + 512 + aRowOff;   // zc (layer 1)
    const uint32_t aHi2 = smb + SM_A + 0   + aRowOff;   // h1 (layer 2)
    const uint32_t bBase = smb + SM_BS +
        (uint32_t)((nbase + (l & 7) + ((l >> 4) << 3)) * BSTR + ((l >> 3) & 1) * 16);

    // first tile's B pipeline starts immediately
    preload(bsWrite, g_w1pk + (size_t)(blockIdx.x % P_) * 131072, tid);

    #pragma unroll 1
    for (int tile = blockIdx.x; tile < NTILE; tile += NCTA) {
        const int p = tile % P_, b0 = (tile / P_) * 64;
        const int m = p / 10, nn = p - m * 10;
        const unsigned char* g1 = g_w1pk + (size_t)p * 131072;
        const unsigned char* g2 = g_w2pk + (size_t)p * 524288;
        const unsigned char* g1next =
            (tile + NCTA < NTILE) ? g_w1pk + (size_t)((tile + NCTA) % P_) * 131072 : nullptr;

        if (tile != (int)blockIdx.x) __syncthreads();   // smem rewrite vs prev epilogue

        if (tid < 64)  ys[tid] = y[(size_t)(b0 + tid) * 10 + nn];
        if (tid < 128) idxs[tid] = (tid < 64) ? idxL[m * 64 + tid] : idxR[m * 64 + (tid - 64)];
        for (int i = tid; i < 512; i += 256) {
            b1s[i] = b1[(size_t)p * 512 + i];
            b2s[i] = b2[(size_t)p * 512 + i];
            w3s[i] = W3[(size_t)p * 512 + i];
        }
        __syncthreads();

        // zc gather -> fp16 at bytes [512,768) of each A row (layer-1-safe hole)
        {
            int row = tid >> 2, cb = (tid & 3) * 32;
            const float* zl = zL + (size_t)(b0 + row) * 512;
            const float* zr = zR + (size_t)(b0 + row) * 512;
            char* rp = sm + SM_A + (size_t)row * H1STR;
            #pragma unroll
            for (int jp = 0; jp < 16; jp++) {
                int j0 = cb + jp * 2;
                float v0 = (j0 < 64) ? zl[idxs[j0]] : zr[idxs[j0]];
                float v1 = (j0 + 1 < 64) ? zl[idxs[j0 + 1]] : zr[idxs[j0 + 1]];
                *(uint32_t*)(rp + 512 + j0 * 2) = pkh(v0, v1);
            }
        }
        // visibility: first in-gemm __syncthreads precedes all ldsm reads

        float acc[2][8][4];
        const float* W1p = W1 + (size_t)p * FIN * 512;

        // ---------- layer 1 ----------
        #pragma unroll 1
        for (int nc = 0; nc < 2; nc++) {
            #pragma unroll
            for (int a = 0; a < 2; a++)
                #pragma unroll
                for (int b = 0; b < 8; b++)
                    #pragma unroll
                    for (int q = 0; q < 4; q++) acc[a][b][q] = 0.f;

            const unsigned char* nxt = (nc == 0) ? (g1 + 16384) : g2;
            gemm1p<4>(acc, aHi1, bBase, bsWrite, g1 + nc * 16384, nxt, tid);
            __syncthreads();   // zc reads complete before epilogue writes below

            #pragma unroll
            for (int mt = 0; mt < 2; mt++) {
                int r0 = mbase + mt * 16 + lr;
                const float* wy0 = W1p + (size_t)ys[r0] * 512;
                const float* wy1 = W1p + (size_t)ys[r0 + 8] * 512;
                char* rp0 = sm + SM_A + (size_t)r0 * H1STR;
                char* rp1 = sm + SM_A + (size_t)(r0 + 8) * H1STR;
                #pragma unroll
                for (int nt = 0; nt < 8; nt++) {
                    int col = nc * 256 + nbase + nt * 8 + (l & 3) * 2;
                    float2 bv = *(const float2*)(b1s + col);
                    float x0 = fmaxf(acc[mt][nt][0] + wy0[col]     + bv.x, 0.f);
                    float x1 = fmaxf(acc[mt][nt][1] + wy0[col + 1] + bv.y, 0.f);
                    float x2 = fmaxf(acc[mt][nt][2] + wy1[col]     + bv.x, 0.f);
                    float x3 = fmaxf(acc[mt][nt][3] + wy1[col + 1] + bv.y, 0.f);
                    *(uint32_t*)(rp0 + col * 2) = pkh(x0, x1);
                    *(uint32_t*)(rp1 + col * 2) = pkh(x2, x3);
                }
            }
        }
        // h1 visibility: first in-gemm __syncthreads of layer 2

        // ---------- layer 2 + fused W3 ----------
        float po[2][2] = {{0.f, 0.f}, {0.f, 0.f}};

        #pragma unroll 1
        for (int nc = 0; nc < 2; nc++) {
            #pragma unroll
            for (int a = 0; a < 2; a++)
                #pragma unroll
                for (int b = 0; b < 8; b++)
                    #pragma unroll
                    for (int q = 0; q < 4; q++) acc[a][b][q] = 0.f;

            const unsigned char* nxt = (nc == 0) ? (g2 + 16384) : g1next;
            gemm1p<16>(acc, aHi2, bBase, bsWrite, g2 + nc * 16384, nxt, tid);

            #pragma unroll
            for (int mt = 0; mt < 2; mt++) {
                #pragma unroll
                for (int nt = 0; nt < 8; nt++) {
                    int col = nc * 256 + nbase + nt * 8 + (l & 3) * 2;
                    float2 bv = *(const float2*)(b2s + col);
                    float2 wv = *(const float2*)(w3s + col);
                    po[mt][0] += fmaxf(acc[mt][nt][0] + bv.x, 0.f) * wv.x
                               + fmaxf(acc[mt][nt][1] + bv.y, 0.f) * wv.y;
                    po[mt][1] += fmaxf(acc[mt][nt][2] + bv.x, 0.f) * wv.x
                               + fmaxf(acc[mt][nt][3] + bv.y, 0.f) * wv.y;
                }
            }
        }

        // 4 n-warps hold 128-col partials -> quad reduce + atomicAdd onto b3-init out
        #pragma unroll
        for (int mt = 0; mt < 2; mt++)
            #pragma unroll
            for (int h = 0; h < 2; h++) {
                float v = po[mt][h];
                v += __shfl_xor_sync(0xffffffffu, v, 1);
                v += __shfl_xor_sync(0xffffffffu, v, 2);
                if ((l & 3) == 0) {
                    int row = mbase + mt * 16 + lr + h * 8;
                    atomicAdd(out + (size_t)(b0 + row) * P_ + p, v);
                }
            }
    }
}

// ---------------- host ----------------
extern "C" void kernel_launch(void* const* d_in, const int* in_sizes, int n_in,
                              void* d_out, int out_size)
{
    (void)in_sizes; (void)n_in; (void)out_size;
    const int*   y    = (const int*)  d_in[0];
    const float* zL   = (const float*)d_in[1];
    const float* zR   = (const float*)d_in[2];
    const int*   idxL = (const int*)  d_in[3];
    const int*   idxR = (const int*)  d_in[4];
    const float* W1   = (const float*)d_in[5];
    const float* b1   = (const float*)d_in[6];
    const float* W2   = (const float*)d_in[7];
    const float* b2   = (const float*)d_in[8];
    const float* W3   = (const float*)d_in[9];
    const float* b3   = (const float*)d_in[10];
    float* out = (float*)d_out;

    cudaFuncSetAttribute(mc_main, cudaFuncAttributeMaxDynamicSharedMemorySize, SMEM_TOTAL);

    prep_kernel<<<3840, 256>>>(W1, W2, b3, out);   // 3200 pack + 640 out-init blocks
    mc_main<<<NCTA, 256, SMEM_TOTAL>>>(y, zL, zR, idxL, idxR, W1, b1, b2, W3, out);
}

// round 16
// speedup vs baseline: 1.0583x; 1.0583x over previous
#include <cuda_runtime.h>
#include <cuda_fp16.h>
#include <cstdint>

// ---------------- problem constants ----------------
#define B_TOT 2048
#define P_    80
#define FIN   138

// ---------------- packed fp16 weight image ----------------
// Per n row, per k32 tile: 64B = 32 fp16. layout: [p][kt][nc(2)][n(256)][64B]
__device__ __align__(1024) unsigned char g_w1pk[(size_t)10485760];   // 80*4*2*256*64
__device__ __align__(1024) unsigned char g_w2pk[(size_t)41943040];   // 80*16*2*256*64

// ---------------- smem layout (bytes) ----------------
// A rows (64): [0,1024) fp16 x512 (h1; zc overlay at +512 for layer 1) + 16 pad
#define H1STR 1040
#define SM_A    0                    // 64*1040 = 66560
#define BSTR  80                     // 64B data + 16 pad (conflict-free ldsm)
#define BBUF  20480                  // 256 rows * 80
#define SM_BS   66560                // 2*BBUF = 40960
#define SM_YS   107520
#define SM_IDX  107776
#define SM_B1   108288               // b1 staging; reused as part[4][64] in final epilogue
#define SM_B2   110336
#define SM_W3   112384
#define SMEM_TOTAL 114432            // x2 CTAs = 223.5 KB <= 228 KB/SM

// ---------------- helpers ----------------
__device__ __forceinline__ void cp16s(uint32_t dst, const void* src) {
    asm volatile("cp.async.cg.shared.global [%0], [%1], 16;" :: "r"(dst), "l"(src));
}
__device__ __forceinline__ void cp_commit() { asm volatile("cp.async.commit_group;"); }
__device__ __forceinline__ void cp_wait0()  { asm volatile("cp.async.wait_group 0;"); }

__device__ __forceinline__ void ldsm4(uint32_t* r, uint32_t addr) {
    asm volatile("ldmatrix.sync.aligned.m8n8.x4.shared.b16 {%0,%1,%2,%3}, [%4];"
        : "=r"(r[0]), "=r"(r[1]), "=r"(r[2]), "=r"(r[3]) : "r"(addr));
}
__device__ __forceinline__ void mma_f16(float* c, const uint32_t* a, const uint32_t* b) {
    asm volatile(
        "mma.sync.aligned.m16n8k16.row.col.f32.f16.f16.f32 "
        "{%0,%1,%2,%3}, {%4,%5,%6,%7}, {%8,%9}, {%0,%1,%2,%3};"
        : "+f"(c[0]), "+f"(c[1]), "+f"(c[2]), "+f"(c[3])
        : "r"(a[0]), "r"(a[1]), "r"(a[2]), "r"(a[3]), "r"(b[0]), "r"(b[1]));
}
__device__ __forceinline__ uint32_t pkh(float x0, float x1) {
    __half2 v = __floats2half2_rn(x0, x1);
    return *reinterpret_cast<uint32_t*>(&v);
}

// issue stage-0 load of a segment into buffer 0 (one cp.async group)
__device__ __forceinline__ void preload(uint32_t bsWrite, const unsigned char* g, int tid) {
    #pragma unroll
    for (int r = 0; r < 4; r++) {
        int i = tid + r * 256;
        cp16s(bsWrite + (uint32_t)((i >> 2) * BSTR + (i & 3) * 16), g + (size_t)i * 16);
    }
    cp_commit();
}

// ---------------- core GEMM: acc(64x256) += A(fp16) x B(fp16), k32 stages ------
// Stage 0 of gsrc must already be in flight. Last stage prefetches stage 0 of
// gnext (if non-null) into buffer 0 — keeps the B pipeline hot across segments.
template<int NST>
__device__ __forceinline__ void gemm1p(
    float acc[2][8][4], uint32_t aHi,
    uint32_t bBase, uint32_t bsWrite,
    const unsigned char* __restrict__ gsrc,
    const unsigned char* __restrict__ gnext, int tid)
{
    #pragma unroll 1
    for (int s = 0; s < NST; s++) {
        cp_wait0();
        __syncthreads();
        const unsigned char* pf = (s + 1 < NST) ? gsrc + (size_t)(s + 1) * 32768 : gnext;
        if (pf) {
            uint32_t wd = bsWrite + (uint32_t)(((s + 1) & 1) * BBUF);
            #pragma unroll
            for (int r = 0; r < 4; r++) {
                int i = tid + r * 256;
                cp16s(wd + (uint32_t)((i >> 2) * BSTR + (i & 3) * 16), pf + (size_t)i * 16);
            }
        }
        cp_commit();   // exactly one group per stage (possibly empty at the very end)

        const uint32_t bb = bBase + (uint32_t)((s & 1) * BBUF);

        #pragma unroll
        for (int t = 0; t < 2; t++) {
            uint32_t ah[2][4];
            ldsm4(ah[0], aHi + (uint32_t)(s * 64 + t * 32));
            ldsm4(ah[1], aHi + (uint32_t)(16 * H1STR + s * 64 + t * 32));
            uint32_t bh[4][4];
            #pragma unroll
            for (int q = 0; q < 4; q++)
                ldsm4(bh[q], bb + (uint32_t)(q * 16 * BSTR + t * 32));
            #pragma unroll
            for (int nt = 0; nt < 8; nt++) {
                const uint32_t* bf = &bh[nt >> 1][(nt & 1) * 2];
                mma_f16(acc[0][nt], ah[0], bf);
                mma_f16(acc[1][nt], ah[1], bf);
            }
        }
    }
}

// ---------------- prep: fp32 weights -> packed K-major fp16 rows ----------------
extern "C" __global__ void __launch_bounds__(256)
prep_kernel(const float* __restrict__ W1, const float* __restrict__ W2)
{
    int j = blockIdx.x;
    int tid = threadIdx.x;
    const float* src;
    unsigned char* dst;
    if (j < 640) {                               // W1: (p, kt 0..3, nc)
        int nc = j & 1, kt = (j >> 1) & 3, p = j >> 3;
        src = W1 + ((size_t)p * FIN + 10 + kt * 32) * 512 + nc * 256;
        dst = g_w1pk + (size_t)p * 131072 + (size_t)kt * 32768 + (size_t)nc * 16384;
    } else {                                     // W2: (p, kt 0..15, nc)
        int q = j - 640;
        int nc = q & 1, kt = (q >> 1) & 15, p = q >> 5;
        src = W2 + ((size_t)p * 512 + kt * 32) * 512 + nc * 256;
        dst = g_w2pk + (size_t)p * 524288 + (size_t)kt * 32768 + (size_t)nc * 16384;
    }
    uint32_t wdat[16];
    #pragma unroll
    for (int i = 0; i < 16; i++) {
        float v0 = src[(size_t)(2 * i) * 512 + tid];
        float v1 = src[(size_t)(2 * i + 1) * 512 + tid];
        wdat[i] = pkh(v0, v1);
    }
    uint4* d = (uint4*)(dst + (size_t)tid * 64);
    #pragma unroll
    for (int r = 0; r < 4; r++)
        d[r] = make_uint4(wdat[r * 4], wdat[r * 4 + 1], wdat[r * 4 + 2], wdat[r * 4 + 3]);
}

// ---------------- main ----------------
extern "C" __global__ void __launch_bounds__(256, 2)
mc_main(const int* __restrict__ y, const float* __restrict__ zL, const float* __restrict__ zR,
        const int* __restrict__ idxL, const int* __restrict__ idxR,
        const float* __restrict__ W1, const float* __restrict__ b1,
        const float* __restrict__ b2, const float* __restrict__ W3,
        const float* __restrict__ b3, float* __restrict__ out)
{
    extern __shared__ char sm[];
    const uint32_t smb = (uint32_t)__cvta_generic_to_shared(sm);
    int*   ys   = (int*)(sm + SM_YS);
    int*   idxs = (int*)(sm + SM_IDX);
    float* b1s  = (float*)(sm + SM_B1);
    float* b2s  = (float*)(sm + SM_B2);
    float* w3s  = (float*)(sm + SM_W3);

    const int p = blockIdx.x, b0 = blockIdx.y * 64;
    const int m = p / 10, nn = p - m * 10;
    const int tid = threadIdx.x, l = tid & 31, w = tid >> 5;
    const int mbase = (w >> 2) * 32, nbase = (w & 3) * 64;
    const int lr = l >> 2;

    const unsigned char* g1 = g_w1pk + (size_t)p * 131072;
    const unsigned char* g2 = g_w2pk + (size_t)p * 524288;
    const uint32_t bsWrite = smb + SM_BS;

    if (tid < 64)  ys[tid] = y[(size_t)(b0 + tid) * 10 + nn];
    if (tid < 128) idxs[tid] = (tid < 64) ? idxL[m * 64 + tid] : idxR[m * 64 + (tid - 64)];
    for (int i = tid; i < 512; i += 256) {
        b1s[i] = b1[(size_t)p * 512 + i];
        b2s[i] = b2[(size_t)p * 512 + i];
        w3s[i] = W3[(size_t)p * 512 + i];
    }
    __syncthreads();

    preload(bsWrite, g1, tid);       // B pipeline starts before the zc gather

    // zc gather -> fp16, overlaid at bytes [512,768) of each A row (layer-1 hole)
    {
        int row = tid >> 2, cb = (tid & 3) * 32;
        const float* zl = zL + (size_t)(b0 + row) * 512;
        const float* zr = zR + (size_t)(b0 + row) * 512;
        char* rp = sm + SM_A + (size_t)row * H1STR;
        #pragma unroll
        for (int jp = 0; jp < 16; jp++) {
            int j0 = cb + jp * 2;
            float v0 = (j0 < 64) ? zl[idxs[j0]] : zr[idxs[j0]];
            float v1 = (j0 + 1 < 64) ? zl[idxs[j0 + 1]] : zr[idxs[j0 + 1]];
            *(uint32_t*)(rp + 512 + j0 * 2) = pkh(v0, v1);
        }
    }
    // visibility: first in-gemm __syncthreads precedes all ldsm reads

    const uint32_t aRowOff = (uint32_t)((mbase + (l & 15)) * H1STR + (l >> 4) * 16);
    const uint32_t aHi1 = smb + SM_A + 512 + aRowOff;   // zc (layer 1)
    const uint32_t aHi2 = smb + SM_A + 0   + aRowOff;   // h1 (layer 2)
    const uint32_t bBase = smb + SM_BS +
        (uint32_t)((nbase + (l & 7) + ((l >> 4) << 3)) * BSTR + ((l >> 3) & 1) * 16);

    float acc[2][8][4];
    const float* W1p = W1 + (size_t)p * FIN * 512;

    // ---------- layer 1 ----------
    #pragma unroll 1
    for (int nc = 0; nc < 2; nc++) {
        #pragma unroll
        for (int a = 0; a < 2; a++)
            #pragma unroll
            for (int b = 0; b < 8; b++)
                #pragma unroll
                for (int q = 0; q < 4; q++) acc[a][b][q] = 0.f;

        const unsigned char* nxt = (nc == 0) ? (g1 + 16384) : g2;
        gemm1p<4>(acc, aHi1, bBase, bsWrite, g1 + nc * 16384, nxt, tid);
        __syncthreads();   // zc reads complete before epilogue writes below

        #pragma unroll
        for (int mt = 0; mt < 2; mt++) {
            int r0 = mbase + mt * 16 + lr;
            const float* wy0 = W1p + (size_t)ys[r0] * 512;
            const float* wy1 = W1p + (size_t)ys[r0 + 8] * 512;
            char* rp0 = sm + SM_A + (size_t)r0 * H1STR;
            char* rp1 = sm + SM_A + (size_t)(r0 + 8) * H1STR;
            #pragma unroll
            for (int nt = 0; nt < 8; nt++) {
                int col = nc * 256 + nbase + nt * 8 + (l & 3) * 2;
                float2 bv = *(const float2*)(b1s + col);
                float x0 = fmaxf(acc[mt][nt][0] + wy0[col]     + bv.x, 0.f);
                float x1 = fmaxf(acc[mt][nt][1] + wy0[col + 1] + bv.y, 0.f);
                float x2 = fmaxf(acc[mt][nt][2] + wy1[col]     + bv.x, 0.f);
                float x3 = fmaxf(acc[mt][nt][3] + wy1[col + 1] + bv.y, 0.f);
                *(uint32_t*)(rp0 + col * 2) = pkh(x0, x1);
                *(uint32_t*)(rp1 + col * 2) = pkh(x2, x3);
            }
        }
    }
    // h1 visibility: first in-gemm __syncthreads of layer 2
    // (b1s is dead from here on; its smem is reused as the partial buffer below)

    // ---------- layer 2 + fused W3 ----------
    float po[2][2] = {{0.f, 0.f}, {0.f, 0.f}};

    #pragma unroll 1
    for (int nc = 0; nc < 2; nc++) {
        #pragma unroll
        for (int a = 0; a < 2; a++)
            #pragma unroll
            for (int b = 0; b < 8; b++)
                #pragma unroll
                for (int q = 0; q < 4; q++) acc[a][b][q] = 0.f;

        const unsigned char* nxt = (nc == 0) ? (g2 + 16384) : nullptr;
        gemm1p<16>(acc, aHi2, bBase, bsWrite, g2 + nc * 16384, nxt, tid);

        #pragma unroll
        for (int mt = 0; mt < 2; mt++) {
            #pragma unroll
            for (int nt = 0; nt < 8; nt++) {
                int col = nc * 256 + nbase + nt * 8 + (l & 3) * 2;
                float2 bv = *(const float2*)(b2s + col);
                float2 wv = *(const float2*)(w3s + col);
                po[mt][0] += fmaxf(acc[mt][nt][0] + bv.x, 0.f) * wv.x
                           + fmaxf(acc[mt][nt][1] + bv.y, 0.f) * wv.y;
                po[mt][1] += fmaxf(acc[mt][nt][2] + bv.x, 0.f) * wv.x
                           + fmaxf(acc[mt][nt][3] + bv.y, 0.f) * wv.y;
            }
        }
    }

    // atomic-free reduction: quad-reduce, park 4 n-warp partials in smem
    // (reusing dead b1s region), then 64 threads sum + b3 and store directly.
    float* part = b1s;               // part[4][64]
    #pragma unroll
    for (int mt = 0; mt < 2; mt++)
        #pragma unroll
        for (int h = 0; h < 2; h++) {
            float v = po[mt][h];
            v += __shfl_xor_sync(0xffffffffu, v, 1);
            v += __shfl_xor_sync(0xffffffffu, v, 2);
            if ((l & 3) == 0) {
                int row = mbase + mt * 16 + lr + h * 8;
                part[(w & 3) * 64 + row] = v;
            }
        }
    __syncthreads();
    if (tid < 64) {
        float s = part[tid] + part[64 + tid] + part[128 + tid] + part[192 + tid];
        out[(size_t)(b0 + tid) * P_ + p] = s + b3[p];
    }
}

// ---------------- host ----------------
extern "C" void kernel_launch(void* const* d_in, const int* in_sizes, int n_in,
                              void* d_out, int out_size)
{
    (void)in_sizes; (void)n_in; (void)out_size;
    const int*   y    = (const int*)  d_in[0];
    const float* zL   = (const float*)d_in[1];
    const float* zR   = (const float*)d_in[2];
    const int*   idxL = (const int*)  d_in[3];
    const int*   idxR = (const int*)  d_in[4];
    const float* W1   = (const float*)d_in[5];
    const float* b1   = (const float*)d_in[6];
    const float* W2   = (const float*)d_in[7];
    const float* b2   = (const float*)d_in[8];
    const float* W3   = (const float*)d_in[9];
    const float* b3   = (const float*)d_in[10];
    float* out = (float*)d_out;

    cudaFuncSetAttribute(mc_main, cudaFuncAttributeMaxDynamicSharedMemorySize, SMEM_TOTAL);

    prep_kernel<<<3200, 256>>>(W1, W2);
    dim3 grid(P_, B_TOT / 64);
    mc_main<<<grid, 256, SMEM_TOTAL>>>(y, zL, zR, idxL, idxR, W1, b1, b2, W3, b3, out);
}

// round 17
// speedup vs baseline: 1.1003x; 1.0397x over previous
#include <cuda_runtime.h>
#include <cuda_fp16.h>
#include <cstdint>

// ---------------- problem constants ----------------
#define B_TOT 2048
#define P_    80
#define FIN   138

// ---------------- packed fp16 weight image ----------------
// Per n row, per k32 tile: 64B = 32 fp16. layout: [p][kt][nc(2)][n(256)][64B]
__device__ __align__(1024) unsigned char g_w1pk[(size_t)10485760];   // 80*4*2*256*64
__device__ __align__(1024) unsigned char g_w2pk[(size_t)41943040];   // 80*16*2*256*64

// ---------------- smem layout (bytes) ----------------
// A rows (64): [0,1024) fp16 x512 (h1; zc overlay at +512 for layer 1) + 16 pad
#define H1STR 1040
#define SM_A    0                    // 64*1040 = 66560
#define BSTR  80                     // 64B data + 16 pad (conflict-free ldsm)
#define BBUF  20480                  // 256 rows * 80
#define SM_BS   66560                // 2*BBUF = 40960
#define SM_YS   107520
#define SM_IDX  107776
#define SM_B1   108288               // b1 staging; reused as part[4][64] in final epilogue
#define SM_B2   110336
#define SM_W3   112384
#define SMEM_TOTAL 114432            // x2 CTAs = 223.5 KB <= 228 KB/SM

// ---------------- helpers ----------------
__device__ __forceinline__ void cp16s(uint32_t dst, const void* src) {
    asm volatile("cp.async.cg.shared.global [%0], [%1], 16;" :: "r"(dst), "l"(src));
}
__device__ __forceinline__ void cp_commit() { asm volatile("cp.async.commit_group;"); }
__device__ __forceinline__ void cp_wait0()  { asm volatile("cp.async.wait_group 0;"); }

__device__ __forceinline__ void ldsm4(uint32_t* r, uint32_t addr) {
    asm volatile("ldmatrix.sync.aligned.m8n8.x4.shared.b16 {%0,%1,%2,%3}, [%4];"
        : "=r"(r[0]), "=r"(r[1]), "=r"(r[2]), "=r"(r[3]) : "r"(addr));
}
__device__ __forceinline__ void mma_f16(float* c, const uint32_t* a, const uint32_t* b) {
    asm volatile(
        "mma.sync.aligned.m16n8k16.row.col.f32.f16.f16.f32 "
        "{%0,%1,%2,%3}, {%4,%5,%6,%7}, {%8,%9}, {%0,%1,%2,%3};"
        : "+f"(c[0]), "+f"(c[1]), "+f"(c[2]), "+f"(c[3])
        : "r"(a[0]), "r"(a[1]), "r"(a[2]), "r"(a[3]), "r"(b[0]), "r"(b[1]));
}
__device__ __forceinline__ uint32_t pkh(float x0, float x1) {
    __half2 v = __floats2half2_rn(x0, x1);
    return *reinterpret_cast<uint32_t*>(&v);
}

// issue stage-0 load of a segment into buffer 0 (one cp.async group)
__device__ __forceinline__ void preload(uint32_t bsWrite, const unsigned char* g, int tid) {
    #pragma unroll
    for (int r = 0; r < 4; r++) {
        int i = tid + r * 256;
        cp16s(bsWrite + (uint32_t)((i >> 2) * BSTR + (i & 3) * 16), g + (size_t)i * 16);
    }
    cp_commit();
}

// ---------------- core GEMM: acc(64x256) += A(fp16) x B(fp16), k32 stages ------
// Stage 0 of gsrc must already be in flight. Last stage prefetches stage 0 of
// gnext (if non-null) into buffer 0 — keeps the B pipeline hot across segments.
template<int NST>
__device__ __forceinline__ void gemm1p(
    float acc[2][8][4], uint32_t aHi,
    uint32_t bBase, uint32_t bsWrite,
    const unsigned char* __restrict__ gsrc,
    const unsigned char* __restrict__ gnext, int tid)
{
    #pragma unroll 1
    for (int s = 0; s < NST; s++) {
        cp_wait0();
        __syncthreads();
        const unsigned char* pf = (s + 1 < NST) ? gsrc + (size_t)(s + 1) * 32768 : gnext;
        if (pf) {
            uint32_t wd = bsWrite + (uint32_t)(((s + 1) & 1) * BBUF);
            #pragma unroll
            for (int r = 0; r < 4; r++) {
                int i = tid + r * 256;
                cp16s(wd + (uint32_t)((i >> 2) * BSTR + (i & 3) * 16), pf + (size_t)i * 16);
            }
        }
        cp_commit();   // exactly one group per stage (possibly empty at the very end)

        const uint32_t bb = bBase + (uint32_t)((s & 1) * BBUF);

        #pragma unroll
        for (int t = 0; t < 2; t++) {
            uint32_t ah[2][4];
            ldsm4(ah[0], aHi + (uint32_t)(s * 64 + t * 32));
            ldsm4(ah[1], aHi + (uint32_t)(16 * H1STR + s * 64 + t * 32));
            uint32_t bh[4][4];
            #pragma unroll
            for (int q = 0; q < 4; q++)
                ldsm4(bh[q], bb + (uint32_t)(q * 16 * BSTR + t * 32));
            #pragma unroll
            for (int nt = 0; nt < 8; nt++) {
                const uint32_t* bf = &bh[nt >> 1][(nt & 1) * 2];
                mma_f16(acc[0][nt], ah[0], bf);
                mma_f16(acc[1][nt], ah[1], bf);
            }
        }
    }
}

// ---------------- prep: fp32 weights -> packed K-major fp16 rows ----------------
extern "C" __global__ void __launch_bounds__(256)
prep_kernel(const float* __restrict__ W1, const float* __restrict__ W2)
{
    int j = blockIdx.x;
    int tid = threadIdx.x;
    const float* src;
    unsigned char* dst;
    if (j < 640) {                               // W1: (p, kt 0..3, nc)
        int nc = j & 1, kt = (j >> 1) & 3, p = j >> 3;
        src = W1 + ((size_t)p * FIN + 10 + kt * 32) * 512 + nc * 256;
        dst = g_w1pk + (size_t)p * 131072 + (size_t)kt * 32768 + (size_t)nc * 16384;
    } else {                                     // W2: (p, kt 0..15, nc)
        int q = j - 640;
        int nc = q & 1, kt = (q >> 1) & 15, p = q >> 5;
        src = W2 + ((size_t)p * 512 + kt * 32) * 512 + nc * 256;
        dst = g_w2pk + (size_t)p * 524288 + (size_t)kt * 32768 + (size_t)nc * 16384;
    }
    uint32_t wdat[16];
    #pragma unroll
    for (int i = 0; i < 16; i++) {
        float v0 = src[(size_t)(2 * i) * 512 + tid];
        float v1 = src[(size_t)(2 * i + 1) * 512 + tid];
        wdat[i] = pkh(v0, v1);
    }
    uint4* d = (uint4*)(dst + (size_t)tid * 64);
    #pragma unroll
    for (int r = 0; r < 4; r++)
        d[r] = make_uint4(wdat[r * 4], wdat[r * 4 + 1], wdat[r * 4 + 2], wdat[r * 4 + 3]);
}

// ---------------- main ----------------
extern "C" __global__ void __launch_bounds__(256, 2)
mc_main(const int* __restrict__ y, const float* __restrict__ zL, const float* __restrict__ zR,
        const int* __restrict__ idxL, const int* __restrict__ idxR,
        const float* __restrict__ W1, const float* __restrict__ b1,
        const float* __restrict__ b2, const float* __restrict__ W3,
        const float* __restrict__ b3, float* __restrict__ out)
{
    extern __shared__ char sm[];
    const uint32_t smb = (uint32_t)__cvta_generic_to_shared(sm);
    int*   ys   = (int*)(sm + SM_YS);
    int*   idxs = (int*)(sm + SM_IDX);
    float* b1s  = (float*)(sm + SM_B1);
    float* b2s  = (float*)(sm + SM_B2);
    float* w3s  = (float*)(sm + SM_W3);

    const int p = blockIdx.x, b0 = blockIdx.y * 64;
    const int m = p / 10, nn = p - m * 10;
    const int tid = threadIdx.x, l = tid & 31, w = tid >> 5;
    const int mbase = (w >> 2) * 32, nbase = (w & 3) * 64;
    const int lr = l >> 2;

    const unsigned char* g1 = g_w1pk + (size_t)p * 131072;
    const unsigned char* g2 = g_w2pk + (size_t)p * 524288;
    const uint32_t bsWrite = smb + SM_BS;

    preload(bsWrite, g1, tid);       // B pipeline starts before ANY smem staging

    if (tid < 64)  ys[tid] = y[(size_t)(b0 + tid) * 10 + nn];
    if (tid < 128) idxs[tid] = (tid < 64) ? idxL[m * 64 + tid] : idxR[m * 64 + (tid - 64)];
    for (int i = tid; i < 512; i += 256) {
        b1s[i] = b1[(size_t)p * 512 + i];
        b2s[i] = b2[(size_t)p * 512 + i];
        w3s[i] = W3[(size_t)p * 512 + i];
    }
    __syncthreads();

    // zc gather -> fp16, overlaid at bytes [512,768) of each A row (layer-1 hole)
    {
        int row = tid >> 2, cb = (tid & 3) * 32;
        const float* zl = zL + (size_t)(b0 + row) * 512;
        const float* zr = zR + (size_t)(b0 + row) * 512;
        char* rp = sm + SM_A + (size_t)row * H1STR;
        #pragma unroll
        for (int jp = 0; jp < 16; jp++) {
            int j0 = cb + jp * 2;
            float v0 = (j0 < 64) ? zl[idxs[j0]] : zr[idxs[j0]];
            float v1 = (j0 + 1 < 64) ? zl[idxs[j0 + 1]] : zr[idxs[j0 + 1]];
            *(uint32_t*)(rp + 512 + j0 * 2) = pkh(v0, v1);
        }
    }
    // visibility: first in-gemm __syncthreads precedes all ldsm reads

    const uint32_t aRowOff = (uint32_t)((mbase + (l & 15)) * H1STR + (l >> 4) * 16);
    const uint32_t aHi1 = smb + SM_A + 512 + aRowOff;   // zc (layer 1)
    const uint32_t aHi2 = smb + SM_A + 0   + aRowOff;   // h1 (layer 2)
    const uint32_t bBase = smb + SM_BS +
        (uint32_t)((nbase + (l & 7) + ((l >> 4) << 3)) * BSTR + ((l >> 3) & 1) * 16);

    float acc[2][8][4];
    const float* W1p = W1 + (size_t)p * FIN * 512;

    // ---------- layer 1 ----------
    #pragma unroll 1
    for (int nc = 0; nc < 2; nc++) {
        #pragma unroll
        for (int a = 0; a < 2; a++)
            #pragma unroll
            for (int b = 0; b < 8; b++)
                #pragma unroll
                for (int q = 0; q < 4; q++) acc[a][b][q] = 0.f;

        const unsigned char* nxt = (nc == 0) ? (g1 + 16384) : g2;
        gemm1p<4>(acc, aHi1, bBase, bsWrite, g1 + nc * 16384, nxt, tid);
        __syncthreads();   // zc reads complete before epilogue writes below

        #pragma unroll
        for (int mt = 0; mt < 2; mt++) {
            int r0 = mbase + mt * 16 + lr;
            const float* wy0 = W1p + (size_t)ys[r0] * 512;
            const float* wy1 = W1p + (size_t)ys[r0 + 8] * 512;
            char* rp0 = sm + SM_A + (size_t)r0 * H1STR;
            char* rp1 = sm + SM_A + (size_t)(r0 + 8) * H1STR;
            #pragma unroll
            for (int nt = 0; nt < 8; nt++) {
                int col = nc * 256 + nbase + nt * 8 + (l & 3) * 2;
                float2 bv = *(const float2*)(b1s + col);
                float2 w0 = *(const float2*)(wy0 + col);      // even col -> 8B aligned
                float2 w1v = *(const float2*)(wy1 + col);
                float x0 = fmaxf(acc[mt][nt][0] + w0.x  + bv.x, 0.f);
                float x1 = fmaxf(acc[mt][nt][1] + w0.y  + bv.y, 0.f);
                float x2 = fmaxf(acc[mt][nt][2] + w1v.x + bv.x, 0.f);
                float x3 = fmaxf(acc[mt][nt][3] + w1v.y + bv.y, 0.f);
                *(uint32_t*)(rp0 + col * 2) = pkh(x0, x1);
                *(uint32_t*)(rp1 + col * 2) = pkh(x2, x3);
            }
        }
    }
    // h1 visibility: first in-gemm __syncthreads of layer 2
    // (b1s is dead from here on; its smem is reused as the partial buffer below)

    // ---------- layer 2 + fused W3 ----------
    float po[2][2] = {{0.f, 0.f}, {0.f, 0.f}};

    #pragma unroll 1
    for (int nc = 0; nc < 2; nc++) {
        #pragma unroll
        for (int a = 0; a < 2; a++)
            #pragma unroll
            for (int b = 0; b < 8; b++)
                #pragma unroll
                for (int q = 0; q < 4; q++) acc[a][b][q] = 0.f;

        const unsigned char* nxt = (nc == 0) ? (g2 + 16384) : nullptr;
        gemm1p<16>(acc, aHi2, bBase, bsWrite, g2 + nc * 16384, nxt, tid);

        #pragma unroll
        for (int mt = 0; mt < 2; mt++) {
            #pragma unroll
            for (int nt = 0; nt < 8; nt++) {
                int col = nc * 256 + nbase + nt * 8 + (l & 3) * 2;
                float2 bv = *(const float2*)(b2s + col);
                float2 wv = *(const float2*)(w3s + col);
                po[mt][0] += fmaxf(acc[mt][nt][0] + bv.x, 0.f) * wv.x
                           + fmaxf(acc[mt][nt][1] + bv.y, 0.f) * wv.y;
                po[mt][1] += fmaxf(acc[mt][nt][2] + bv.x, 0.f) * wv.x
                           + fmaxf(acc[mt][nt][3] + bv.y, 0.f) * wv.y;
            }
        }
    }

    // atomic-free reduction: quad-reduce, park 4 n-warp partials in smem
    // (reusing dead b1s region), then 64 threads sum + b3 and store directly.
    const float b3v = b3[p];         // hoisted before the barrier
    float* part = b1s;               // part[4][64]
    #pragma unroll
    for (int mt = 0; mt < 2; mt++)
        #pragma unroll
        for (int h = 0; h < 2; h++) {
            float v = po[mt][h];
            v += __shfl_xor_sync(0xffffffffu, v, 1);
            v += __shfl_xor_sync(0xffffffffu, v, 2);
            if ((l & 3) == 0) {
                int row = mbase + mt * 16 + lr + h * 8;
                part[(w & 3) * 64 + row] = v;
            }
        }
    __syncthreads();
    if (tid < 64) {
        float s = part[tid] + part[64 + tid] + part[128 + tid] + part[192 + tid];
        out[(size_t)(b0 + tid) * P_ + p] = s + b3v;
    }
}

// ---------------- host ----------------
extern "C" void kernel_launch(void* const* d_in, const int* in_sizes, int n_in,
                              void* d_out, int out_size)
{
    (void)in_sizes; (void)n_in; (void)out_size;
    const int*   y    = (const int*)  d_in[0];
    const float* zL   = (const float*)d_in[1];
    const float* zR   = (const float*)d_in[2];
    const int*   idxL = (const int*)  d_in[3];
    const int*   idxR = (const int*)  d_in[4];
    const float* W1   = (const float*)d_in[5];
    const float* b1   = (const float*)d_in[6];
    const float* W2   = (const float*)d_in[7];
    const float* b2   = (const float*)d_in[8];
    const float* W3   = (const float*)d_in[9];
    const float* b3   = (const float*)d_in[10];
    float* out = (float*)d_out;

    cudaFuncSetAttribute(mc_main, cudaFuncAttributeMaxDynamicSharedMemorySize, SMEM_TOTAL);

    prep_kernel<<<3200, 256>>>(W1, W2);
    dim3 grid(P_, B_TOT / 64);
    mc_main<<<grid, 256, SMEM_TOTAL>>>(y, zL, zR, idxL, idxR, W1, b1, b2, W3, b3, out);
}